// round 4
// baseline (speedup 1.0000x reference)
#include <cuda_runtime.h>
#include <cstdint>

#define NB 8
#define NA 49104
#define NC 90
#define IMGF 512.0f
#define SCORE_THR 0.2f
#define THR_BITS 0x3E4CCCCDu   /* bits of 0.2f; valid <=> bits > THR_BITS */
#define IOU_THR 0.2f
#define K_PRE 1000
#define K_OUT 100
#define NROW (NB * NA)
#define NBINS 10240
#define B0 0x7C999u            /* THR_BITS >> 11 */
#define CAND_CAP 2048
#define ROWS_PB 64

typedef unsigned long long ull;

// ---------------- scratch (zero-initialized at module load; fused kernel
// re-zeroes g_hist at the end of every run, so every replay sees zeros) ----
__device__ float g_maxs[NROW];
__device__ unsigned char g_cls[NROW];
__device__ int g_hist[NB * NBINS];

// ---------------- K1: smem-staged max/argmax + per-image score histogram ----
__global__ void __launch_bounds__(256) k_maxarg(const float* __restrict__ cls) {
    __shared__ float s[ROWS_PB * NC];   // 23040 B
    const int blk = blockIdx.x;
    const int tid = threadIdx.x;

    const float4* src = reinterpret_cast<const float4*>(cls + (size_t)blk * ROWS_PB * NC);
    float4* dst = reinterpret_cast<float4*>(s);
#pragma unroll
    for (int i = 0; i < 6; i++) {
        int k = tid + i * 256;
        if (k < ROWS_PB * NC / 4) dst[k] = src[k];
    }
    __syncthreads();

    const int warp = tid >> 5, lane = tid & 31;
#pragma unroll
    for (int r = 0; r < 8; r++) {
        int row = warp * 8 + r;
        const float* p = s + row * NC;
        float v0 = p[lane];
        float v1 = p[lane + 32];
        ull k0 = ((ull)__float_as_uint(v0) << 32) | (unsigned)(89 - lane);
        ull k1 = ((ull)__float_as_uint(v1) << 32) | (unsigned)(57 - lane);
        ull key = k0 > k1 ? k0 : k1;
        if (lane < 26) {
            float v2 = p[lane + 64];
            ull k2 = ((ull)__float_as_uint(v2) << 32) | (unsigned)(25 - lane);
            if (k2 > key) key = k2;
        }
#pragma unroll
        for (int off = 16; off; off >>= 1) {
            ull o = __shfl_xor_sync(0xffffffffu, key, off);
            if (o > key) key = o;
        }
        if (lane == 0) {
            int grow = blk * ROWS_PB + row;
            unsigned bits = (unsigned)(key >> 32);
            g_maxs[grow] = __uint_as_float(bits);
            g_cls[grow] = (unsigned char)(89 - (int)(key & 0xFFu));
            if (bits > THR_BITS) {
                int b = grow / NA;
                int bin = min((int)((bits >> 11) - B0), NBINS - 1);
                atomicAdd(&g_hist[b * NBINS + bin], 1);
            }
        }
    }
}

// ---------------- K2: fused threshold + compact + sort + NMS + output ------
__global__ void __launch_bounds__(1024, 1)
k_fused(const float* __restrict__ loc,
        const float* __restrict__ anchors,
        float* __restrict__ out) {
    const int b = blockIdx.x;
    const int tid = threadIdx.x;
    const int lane = tid & 31, w = tid >> 5;
    const int NT = 1024;

    __shared__ ull buf[CAND_CAP];
    __shared__ float4 sbox[K_PRE];
    __shared__ float sval[K_PRE];
    __shared__ int scls[K_PRE];
    __shared__ float4 kbox[K_OUT];
    __shared__ float karea[K_OUT];
    __shared__ int kcls[K_OUT];
    __shared__ short kept[K_OUT];
    __shared__ int wtot[32];
    __shared__ int s_nk, s_cnt;
    __shared__ unsigned s_thr;

    // ---- threshold from histogram (each thread owns 10 descending bins) ----
    int* h = g_hist + b * NBINS;
    int loc10[10];
    int ssum = 0;
#pragma unroll
    for (int j = 0; j < 10; j++) {
        int bi = NBINS - 1 - (tid * 10 + j);
        loc10[j] = h[bi];
        h[bi] = 0;                 // re-zero for the next run (disjoint per thread)
        ssum += loc10[j];
    }
    int ps = ssum;
#pragma unroll
    for (int off = 1; off < 32; off <<= 1) {
        int t = __shfl_up_sync(0xffffffffu, ps, off);
        if (lane >= off) ps += t;
    }
    if (lane == 31) wtot[w] = ps;
    if (tid == 0) { s_thr = 0xFFFFFFFFu; s_nk = 0; s_cnt = 0; }
    __syncthreads();
    if (w == 0) {
        int v = wtot[lane];
#pragma unroll
        for (int off = 1; off < 32; off <<= 1) {
            int t = __shfl_up_sync(0xffffffffu, v, off);
            if (lane >= off) v += t;
        }
        wtot[lane] = v;
    }
    __syncthreads();

    const int total = wtot[31];
    const int Kmax = min(K_PRE, total);
    if (Kmax > 0) {
        int above = (ps - ssum) + (w > 0 ? wtot[w - 1] : 0);
        if (above < Kmax && Kmax <= above + ssum) {
            int cum = above;
#pragma unroll
            for (int j = 0; j < 10; j++) {
                if (cum + loc10[j] >= Kmax) {
                    s_thr = (unsigned)(B0 + (NBINS - 1 - (tid * 10 + j))) << 11;
                    break;
                }
                cum += loc10[j];
            }
        }
    }
    __syncthreads();
    const unsigned thr = s_thr;

    // ---- compaction: scan this image's maxima, keep bits >= thr ----
    const float4* sc4 = reinterpret_cast<const float4*>(g_maxs + (size_t)b * NA);
    const int N4 = NA / 4;   // 12276
    for (int i = tid; i < N4; i += NT) {
        float4 v = sc4[i];
        unsigned kk[4] = { __float_as_uint(v.x), __float_as_uint(v.y),
                           __float_as_uint(v.z), __float_as_uint(v.w) };
#pragma unroll
        for (int c = 0; c < 4; c++) {
            if (kk[c] > THR_BITS && kk[c] >= thr) {
                int pos = atomicAdd(&s_cnt, 1);
                int idx = i * 4 + c;
                if (pos < CAND_CAP)
                    buf[pos] = ((ull)kk[c] << 32) |
                               ((ull)(0xFFFFu - (unsigned)idx) << 16) |
                               (ull)g_cls[(size_t)b * NA + idx];
            }
        }
    }
    __syncthreads();
    const int n = min(s_cnt, CAND_CAP);
    const int K = min(Kmax, n);
    for (int i = n + tid; i < CAND_CAP; i += NT) buf[i] = 0ULL;
    __syncthreads();

    // ---- bitonic sort (descending, 2048), j<=16 phases in registers ----
    for (int k = 2; k <= CAND_CAP; k <<= 1) {
        for (int j = k >> 1; j >= 32; j >>= 1) {
#pragma unroll
            for (int pass = 0; pass < 2; pass++) {
                int i = tid + pass * NT;
                int ixj = i ^ j;
                if (ixj > i) {
                    bool desc = ((i & k) == 0);
                    ull a = buf[i], c2 = buf[ixj];
                    if (desc ? (a < c2) : (a > c2)) { buf[i] = c2; buf[ixj] = a; }
                }
            }
            __syncthreads();
        }
        {
            const int jstart = (k >> 1) < 16 ? (k >> 1) : 16;
#pragma unroll
            for (int s = 0; s < 2; s++) {
                int e = (w + s * 32) * 32 + lane;
                ull v = buf[e];
                bool desc = ((e & k) == 0);
                for (int j = jstart; j; j >>= 1) {
                    ull o = __shfl_xor_sync(0xffffffffu, v, j);
                    bool lower = (lane & j) == 0;
                    if (desc == lower) v = (v > o) ? v : o;
                    else               v = (v < o) ? v : o;
                }
                buf[e] = v;
            }
            __syncthreads();
        }
    }

    // ---- decode top-K candidates ----
    for (int i = tid; i < K_PRE; i += NT) {
        if (i < K) {
            ull key = buf[i];
            unsigned idx = 0xFFFFu - (unsigned)((key >> 16) & 0xFFFFu);
            float score = __uint_as_float((unsigned)(key >> 32));
            float4 an = reinterpret_cast<const float4*>(anchors)[idx];            // y1,x1,y2,x2
            float4 lp = reinterpret_cast<const float4*>(loc)[(size_t)b * NA + idx]; // dy,dx,dh,dw
            float ya = (an.x + an.z) * 0.5f, xa = (an.y + an.w) * 0.5f;
            float ha = an.z - an.x, wa = an.w - an.y;
            float hh = expf(lp.z) * ha;
            float ww = expf(lp.w) * wa;
            float yc = lp.x * ha + ya;
            float xc = lp.y * wa + xa;
            float x1 = fminf(fmaxf(xc - 0.5f * ww, 0.f), IMGF);
            float y1 = fminf(fmaxf(yc - 0.5f * hh, 0.f), IMGF);
            float x2 = fminf(fmaxf(xc + 0.5f * ww, 0.f), IMGF);
            float y2 = fminf(fmaxf(yc + 0.5f * hh, 0.f), IMGF);
            sbox[i] = make_float4(x1, y1, x2, y2);
            sval[i] = score;
            scls[i] = (int)(key & 0xFFFFu);
        } else {
            sbox[i] = make_float4(0.f, 0.f, 0.f, 0.f);
            sval[i] = -1.0f;
            scls[i] = -1;
        }
    }
    __syncthreads();

    // ---- greedy NMS (warp 0; early exit at K_OUT kept) ----
    if (tid < 32) {
        int nk = 0;
        for (int i = 0; i < K && nk < K_OUT; i++) {
            float v = sval[i];
            if (!(v > SCORE_THR)) continue;
            float4 bi = sbox[i];
            int ci = scls[i];
            float ai = (bi.z - bi.x) * (bi.w - bi.y);
            bool sup = false;
#pragma unroll
            for (int r = 0; r < 4; r++) {
                int slot = lane + (r << 5);
                if (slot < nk && kcls[slot] == ci) {
                    float4 bj = kbox[slot];
                    float xx1 = fmaxf(bi.x, bj.x), yy1 = fmaxf(bi.y, bj.y);
                    float xx2 = fminf(bi.z, bj.z), yy2 = fminf(bi.w, bj.w);
                    float in = fmaxf(xx2 - xx1, 0.f) * fmaxf(yy2 - yy1, 0.f);
                    float iou = in / (ai + karea[slot] - in + 1e-8f);
                    if (iou > IOU_THR) sup = true;
                }
            }
            if (__ballot_sync(0xffffffffu, sup) == 0u) {
                if (lane == 0) {
                    kbox[nk] = bi; karea[nk] = ai; kcls[nk] = ci; kept[nk] = (short)i;
                }
                __syncwarp();
                nk++;
            }
        }
        if (lane == 0) s_nk = nk;
    }
    __syncthreads();
    const int nk = s_nk;

    // ---- output: boxes [B,100,4] | scores [B,100] | labels [B,100] ----
    float* oboxes  = out + (size_t)b * K_OUT * 4;
    float* oscores = out + (size_t)NB * K_OUT * 4 + (size_t)b * K_OUT;
    float* olabels = out + (size_t)NB * K_OUT * 5 + (size_t)b * K_OUT;
    for (int s2 = tid; s2 < K_OUT; s2 += NT) {
        if (s2 < nk) {
            int i = kept[s2];
            float4 bb = sbox[i];
            oboxes[s2 * 4 + 0] = bb.x;
            oboxes[s2 * 4 + 1] = bb.y;
            oboxes[s2 * 4 + 2] = bb.z;
            oboxes[s2 * 4 + 3] = bb.w;
            oscores[s2] = sval[i];
            olabels[s2] = (float)scls[i];
        } else {
            oboxes[s2 * 4 + 0] = 0.f;
            oboxes[s2 * 4 + 1] = 0.f;
            oboxes[s2 * 4 + 2] = 1.f;
            oboxes[s2 * 4 + 3] = 1.f;
            oscores[s2] = 0.f;
            olabels[s2] = -1.f;
        }
    }
}

// ---------------- launch ----------------
extern "C" void kernel_launch(void* const* d_in, const int* in_sizes, int n_in,
                              void* d_out, int out_size) {
    const float* cls     = (const float*)d_in[0];
    const float* loc     = (const float*)d_in[1];
    const float* anchors = (const float*)d_in[2];
    float* out = (float*)d_out;

    k_maxarg<<<NROW / ROWS_PB, 256>>>(cls);   // 6138 blocks
    k_fused<<<NB, 1024>>>(loc, anchors, out);
}

// round 5
// speedup vs baseline: 1.1048x; 1.1048x over previous
#include <cuda_runtime.h>
#include <cstdint>

#define NB 8
#define NA 49104
#define NC 90
#define IMGF 512.0f
#define SCORE_THR 0.2f
#define THR_BITS 0x3E4CCCCDu   /* bits of 0.2f; valid <=> bits > THR_BITS */
#define IOU_THR 0.2f
#define K_PRE 1000
#define K_OUT 100
#define NROW (NB * NA)
#define NBINS 10240
#define B0 0x7C999u            /* THR_BITS >> 11 */
#define CAND_CAP 2048
#define ROWS_PB 64
#define M_FAST 256             /* fast-path sorted-prefix target */

typedef unsigned long long ull;

// ---------------- scratch (zero-init at load; k_fused re-zeroes g_hist) ----
__device__ float g_maxs[NROW];
__device__ unsigned char g_cls[NROW];
__device__ int g_hist[NB * NBINS];

// ---------------- K1: smem-staged max/argmax (REDUX) + score histogram ----
__global__ void __launch_bounds__(256) k_maxarg(const float* __restrict__ cls) {
    __shared__ float s[ROWS_PB * NC];   // 23040 B
    const int blk = blockIdx.x;
    const int tid = threadIdx.x;

    const float4* src = reinterpret_cast<const float4*>(cls + (size_t)blk * ROWS_PB * NC);
    float4* dst = reinterpret_cast<float4*>(s);
#pragma unroll
    for (int i = 0; i < 6; i++) {
        int k = tid + i * 256;
        if (k < ROWS_PB * NC / 4) dst[k] = src[k];
    }
    __syncthreads();

    const int warp = tid >> 5, lane = tid & 31;
#pragma unroll
    for (int r = 0; r < 8; r++) {
        int row = warp * 8 + r;
        const float* p = s + row * NC;
        unsigned b0 = __float_as_uint(p[lane]);
        unsigned b1 = __float_as_uint(p[lane + 32]);
        unsigned b2 = (lane < 26) ? __float_as_uint(p[lane + 64]) : 0u;
        unsigned mx = max(b0, max(b1, b2));
        mx = __reduce_max_sync(0xffffffffu, mx);
        unsigned c = 0xFFu;
        if (b2 == mx) c = lane + 64;     // assign large first; smaller overwrite
        if (b1 == mx) c = lane + 32;
        if (b0 == mx) c = lane;
        c = __reduce_min_sync(0xffffffffu, c);
        if (lane == 0) {
            int grow = blk * ROWS_PB + row;
            g_maxs[grow] = __uint_as_float(mx);
            g_cls[grow] = (unsigned char)c;
            if (mx > THR_BITS) {
                int b = grow / NA;
                int bin = min((int)((mx >> 11) - B0), NBINS - 1);
                atomicAdd(&g_hist[b * NBINS + bin], 1);
            }
        }
    }
}

// ---------------- K2: fused thresholds + compact + (small) sort + NMS ------
__global__ void __launch_bounds__(1024, 1)
k_fused(const float* __restrict__ loc,
        const float* __restrict__ anchors,
        float* __restrict__ out) {
    const int b = blockIdx.x;
    const int tid = threadIdx.x;
    const int lane = tid & 31, w = tid >> 5;
    const int NT = 1024;

    __shared__ ull buf[CAND_CAP];
    __shared__ float4 sbox[1024];
    __shared__ float sval[1024];
    __shared__ int scls[1024];
    __shared__ float4 kbox[K_OUT];
    __shared__ float karea[K_OUT];
    __shared__ int kcls[K_OUT];
    __shared__ short kept[K_OUT];
    __shared__ int wtot[32];
    __shared__ int s_nk, s_cnt;
    __shared__ unsigned s_thr[2];   // [0]: rank-m (fast), [1]: rank-K (full)

    // ---- thresholds from histogram (each thread owns 10 descending bins) ----
    int* h = g_hist + b * NBINS;
    int loc10[10];
    int ssum = 0;
#pragma unroll
    for (int j = 0; j < 10; j++) {
        int bi = NBINS - 1 - (tid * 10 + j);
        loc10[j] = h[bi];
        h[bi] = 0;                 // re-zero for next run (disjoint per thread)
        ssum += loc10[j];
    }
    int ps = ssum;
#pragma unroll
    for (int off = 1; off < 32; off <<= 1) {
        int t = __shfl_up_sync(0xffffffffu, ps, off);
        if (lane >= off) ps += t;
    }
    if (lane == 31) wtot[w] = ps;
    if (tid == 0) { s_thr[0] = 0xFFFFFFFFu; s_thr[1] = 0xFFFFFFFFu; s_nk = 0; }
    __syncthreads();
    if (w == 0) {
        int v = wtot[lane];
#pragma unroll
        for (int off = 1; off < 32; off <<= 1) {
            int t = __shfl_up_sync(0xffffffffu, v, off);
            if (lane >= off) v += t;
        }
        wtot[lane] = v;
    }
    __syncthreads();

    const int total = wtot[31];
    const int K = min(K_PRE, total);
    const int m = min(M_FAST, K);
    if (K > 0) {
        int above = (ps - ssum) + (w > 0 ? wtot[w - 1] : 0);
#pragma unroll
        for (int t = 0; t < 2; t++) {
            int r = (t == 0) ? m : K;
            if (above < r && r <= above + ssum) {
                int cum = above;
#pragma unroll
                for (int j = 0; j < 10; j++) {
                    if (cum + loc10[j] >= r) {
                        s_thr[t] = (unsigned)(B0 + (NBINS - 1 - (tid * 10 + j))) << 11;
                        break;
                    }
                    cum += loc10[j];
                }
            }
        }
    }
    __syncthreads();

    const float4* sc4 = reinterpret_cast<const float4*>(g_maxs + (size_t)b * NA);
    const int N4 = NA / 4;   // 12276
    int nfinal = 0;

    for (int round = 0; round < 2; round++) {
        const unsigned thr = s_thr[round];
        // ---- compaction: keys >= thr ----
        if (tid == 0) s_cnt = 0;
        __syncthreads();
        for (int i = tid; i < N4; i += NT) {
            float4 v = sc4[i];
            unsigned kk[4] = { __float_as_uint(v.x), __float_as_uint(v.y),
                               __float_as_uint(v.z), __float_as_uint(v.w) };
#pragma unroll
            for (int c = 0; c < 4; c++) {
                if (kk[c] > THR_BITS && kk[c] >= thr) {
                    int pos = atomicAdd(&s_cnt, 1);
                    int idx = i * 4 + c;
                    if (pos < CAND_CAP)
                        buf[pos] = ((ull)kk[c] << 32) |
                                   ((ull)(0xFFFFu - (unsigned)idx) << 16) |
                                   (ull)g_cls[(size_t)b * NA + idx];
                }
            }
        }
        __syncthreads();
        const int n = min(s_cnt, CAND_CAP);
        if (round == 0 && n > 1024) continue;   // fast path can't hold it

        int SZ = 32;
        while (SZ < n) SZ <<= 1;
        const int L = min(K, n);                // NMS scan limit
        for (int i = n + tid; i < SZ; i += NT) buf[i] = 0ULL;
        __syncthreads();

        // ---- bitonic sort (descending, SZ keys) ----
        for (int k2 = 2; k2 <= SZ; k2 <<= 1) {
            for (int j = k2 >> 1; j >= 32; j >>= 1) {
                for (int t = tid; t < (SZ >> 1); t += NT) {
                    int i = ((t & ~(j - 1)) << 1) | (t & (j - 1));
                    int ixj = i + j;
                    bool desc = ((i & k2) == 0);
                    ull a = buf[i], c2 = buf[ixj];
                    if (desc ? (a < c2) : (a > c2)) { buf[i] = c2; buf[ixj] = a; }
                }
                __syncthreads();
            }
            const int jstart = min(k2 >> 1, 16);
            for (int e = tid; e < SZ; e += NT) {
                ull v = buf[e];
                bool desc = ((e & k2) == 0);
                for (int j = jstart; j; j >>= 1) {
                    ull o = __shfl_xor_sync(0xffffffffu, v, j);
                    bool lower = (lane & j) == 0;
                    if (desc == lower) v = (v > o) ? v : o;
                    else               v = (v < o) ? v : o;
                }
                buf[e] = v;
            }
            __syncthreads();
        }

        // ---- decode the first L candidates ----
        for (int i = tid; i < L; i += NT) {
            ull key = buf[i];
            unsigned idx = 0xFFFFu - (unsigned)((key >> 16) & 0xFFFFu);
            float score = __uint_as_float((unsigned)(key >> 32));
            float4 an = reinterpret_cast<const float4*>(anchors)[idx];             // y1,x1,y2,x2
            float4 lp = reinterpret_cast<const float4*>(loc)[(size_t)b * NA + idx]; // dy,dx,dh,dw
            float ya = (an.x + an.z) * 0.5f, xa = (an.y + an.w) * 0.5f;
            float ha = an.z - an.x, wa = an.w - an.y;
            float hh = expf(lp.z) * ha;
            float ww = expf(lp.w) * wa;
            float yc = lp.x * ha + ya;
            float xc = lp.y * wa + xa;
            float x1 = fminf(fmaxf(xc - 0.5f * ww, 0.f), IMGF);
            float y1 = fminf(fmaxf(yc - 0.5f * hh, 0.f), IMGF);
            float x2 = fminf(fmaxf(xc + 0.5f * ww, 0.f), IMGF);
            float y2 = fminf(fmaxf(yc + 0.5f * hh, 0.f), IMGF);
            sbox[i] = make_float4(x1, y1, x2, y2);
            sval[i] = score;
            scls[i] = (int)(key & 0xFFFFu);
        }
        if (tid == 0) s_nk = 0;
        __syncthreads();

        // ---- greedy NMS (warp 0; early exit at K_OUT kept) ----
        if (tid < 32) {
            int nk = 0;
            for (int i = 0; i < L && nk < K_OUT; i++) {
                float v = sval[i];
                if (!(v > SCORE_THR)) continue;
                float4 bi = sbox[i];
                int ci = scls[i];
                float ai = (bi.z - bi.x) * (bi.w - bi.y);
                bool sup = false;
#pragma unroll
                for (int r = 0; r < 4; r++) {
                    int slot = lane + (r << 5);
                    if (slot < nk && kcls[slot] == ci) {
                        float4 bj = kbox[slot];
                        float xx1 = fmaxf(bi.x, bj.x), yy1 = fmaxf(bi.y, bj.y);
                        float xx2 = fminf(bi.z, bj.z), yy2 = fminf(bi.w, bj.w);
                        float in = fmaxf(xx2 - xx1, 0.f) * fmaxf(yy2 - yy1, 0.f);
                        float iou = in / (ai + karea[slot] - in + 1e-8f);
                        if (iou > IOU_THR) sup = true;
                    }
                }
                if (__ballot_sync(0xffffffffu, sup) == 0u) {
                    if (lane == 0) {
                        kbox[nk] = bi; karea[nk] = ai; kcls[nk] = ci; kept[nk] = (short)i;
                    }
                    __syncwarp();
                    nk++;
                }
            }
            if (lane == 0) s_nk = nk;
        }
        __syncthreads();
        nfinal = s_nk;
        // done if: full round, or found K_OUT, or fast set already covered top-K
        if (round == 1 || nfinal >= K_OUT || n >= K) break;
    }

    const int nk = nfinal;
    // ---- output: boxes [B,100,4] | scores [B,100] | labels [B,100] ----
    float* oboxes  = out + (size_t)b * K_OUT * 4;
    float* oscores = out + (size_t)NB * K_OUT * 4 + (size_t)b * K_OUT;
    float* olabels = out + (size_t)NB * K_OUT * 5 + (size_t)b * K_OUT;
    for (int s2 = tid; s2 < K_OUT; s2 += NT) {
        if (s2 < nk) {
            int i = kept[s2];
            float4 bb = sbox[i];
            oboxes[s2 * 4 + 0] = bb.x;
            oboxes[s2 * 4 + 1] = bb.y;
            oboxes[s2 * 4 + 2] = bb.z;
            oboxes[s2 * 4 + 3] = bb.w;
            oscores[s2] = sval[i];
            olabels[s2] = (float)scls[i];
        } else {
            oboxes[s2 * 4 + 0] = 0.f;
            oboxes[s2 * 4 + 1] = 0.f;
            oboxes[s2 * 4 + 2] = 1.f;
            oboxes[s2 * 4 + 3] = 1.f;
            oscores[s2] = 0.f;
            olabels[s2] = -1.f;
        }
    }
}

// ---------------- launch ----------------
extern "C" void kernel_launch(void* const* d_in, const int* in_sizes, int n_in,
                              void* d_out, int out_size) {
    const float* cls     = (const float*)d_in[0];
    const float* loc     = (const float*)d_in[1];
    const float* anchors = (const float*)d_in[2];
    float* out = (float*)d_out;

    k_maxarg<<<NROW / ROWS_PB, 256>>>(cls);   // 6138 blocks
    k_fused<<<NB, 1024>>>(loc, anchors, out);
}

// round 6
// speedup vs baseline: 1.2900x; 1.1676x over previous
#include <cuda_runtime.h>
#include <cstdint>

#define NB 8
#define NA 49104
#define NC 90
#define IMGF 512.0f
#define SCORE_THR 0.2f
#define THR_BITS 0x3E4CCCCDu   /* bits of 0.2f; valid <=> bits > THR_BITS */
#define IOU_THR 0.2f
#define K_PRE 1000
#define K_OUT 100
#define NROW (NB * NA)
#define NBINS 10240
#define B0 0x7C999u            /* THR_BITS >> 11 */
#define CAND_CAP 2048
#define ROWS_PB 128
#define M_FAST 256             /* fast-path sorted-prefix target & adjacency size */

typedef unsigned long long ull;

// ---------------- scratch (zero-init at load; k_fused re-zeroes g_hist) ----
__device__ float g_maxs[NROW];
__device__ unsigned char g_cls[NROW];
__device__ int g_hist[NB * NBINS];

// ---------------- K1: smem-staged max/argmax (REDUX) + score histogram ----
__global__ void __launch_bounds__(512) k_maxarg(const float* __restrict__ cls) {
    __shared__ float s[ROWS_PB * NC];   // 46080 B (static, < 48KB)
    const int blk = blockIdx.x;
    const int tid = threadIdx.x;

    const float4* src = reinterpret_cast<const float4*>(cls + (size_t)blk * ROWS_PB * NC);
    float4* dst = reinterpret_cast<float4*>(s);
#pragma unroll
    for (int i = 0; i < 6; i++) {
        int k = tid + i * 512;
        if (k < ROWS_PB * NC / 4) dst[k] = src[k];
    }
    __syncthreads();

    const int warp = tid >> 5, lane = tid & 31;
#pragma unroll
    for (int r = 0; r < 8; r++) {
        int row = warp * 8 + r;
        const float* p = s + row * NC;
        unsigned b0 = __float_as_uint(p[lane]);
        unsigned b1 = __float_as_uint(p[lane + 32]);
        unsigned b2 = (lane < 26) ? __float_as_uint(p[lane + 64]) : 0u;
        unsigned mx = max(b0, max(b1, b2));
        mx = __reduce_max_sync(0xffffffffu, mx);
        unsigned c = 0xFFu;
        if (b2 == mx) c = lane + 64;     // larger first; smaller overwrite
        if (b1 == mx) c = lane + 32;
        if (b0 == mx) c = lane;
        c = __reduce_min_sync(0xffffffffu, c);
        if (lane == 0) {
            int grow = blk * ROWS_PB + row;
            g_maxs[grow] = __uint_as_float(mx);
            g_cls[grow] = (unsigned char)c;
            if (mx > THR_BITS) {
                int b = grow / NA;
                int bin = min((int)((mx >> 11) - B0), NBINS - 1);
                atomicAdd(&g_hist[b * NBINS + bin], 1);
            }
        }
    }
}

// ---------------- K2: fused thresholds + compact + sort + bitmask NMS ------
__global__ void __launch_bounds__(1024, 1)
k_fused(const float* __restrict__ loc,
        const float* __restrict__ anchors,
        float* __restrict__ out) {
    const int b = blockIdx.x;
    const int tid = threadIdx.x;
    const int lane = tid & 31, w = tid >> 5;
    const int NT = 1024;

    __shared__ ull buf[CAND_CAP];           // sort keys; reused as adj after decode
    __shared__ float4 sbox[1024];
    __shared__ float sval[1024];
    __shared__ int scls[1024];
    __shared__ float4 kbox[K_OUT];
    __shared__ float karea[K_OUT];
    __shared__ int kcls[K_OUT];
    __shared__ short kept[K_OUT];
    __shared__ int wtot[32];
    __shared__ int s_nk, s_cnt;
    __shared__ unsigned s_thr[2];           // [0]: rank-m (fast), [1]: rank-K (full)

    unsigned* adj = reinterpret_cast<unsigned*>(buf);   // adj[i*8 + w32], 256x8

    // ---- thresholds from histogram (each thread owns 10 descending bins) ----
    int* h = g_hist + b * NBINS;
    int loc10[10];
    int ssum = 0;
#pragma unroll
    for (int j = 0; j < 10; j++) {
        int bi = NBINS - 1 - (tid * 10 + j);
        loc10[j] = h[bi];
        h[bi] = 0;                 // re-zero for next run (disjoint per thread)
        ssum += loc10[j];
    }
    int ps = ssum;
#pragma unroll
    for (int off = 1; off < 32; off <<= 1) {
        int t = __shfl_up_sync(0xffffffffu, ps, off);
        if (lane >= off) ps += t;
    }
    if (lane == 31) wtot[w] = ps;
    if (tid == 0) { s_thr[0] = 0xFFFFFFFFu; s_thr[1] = 0xFFFFFFFFu; s_nk = 0; }
    __syncthreads();
    if (w == 0) {
        int v = wtot[lane];
#pragma unroll
        for (int off = 1; off < 32; off <<= 1) {
            int t = __shfl_up_sync(0xffffffffu, v, off);
            if (lane >= off) v += t;
        }
        wtot[lane] = v;
    }
    __syncthreads();

    const int total = wtot[31];
    const int K = min(K_PRE, total);
    const int m = min(M_FAST, K);
    if (K > 0) {
        int above = (ps - ssum) + (w > 0 ? wtot[w - 1] : 0);
#pragma unroll
        for (int t = 0; t < 2; t++) {
            int r = (t == 0) ? m : K;
            if (above < r && r <= above + ssum) {
                int cum = above;
#pragma unroll
                for (int j = 0; j < 10; j++) {
                    if (cum + loc10[j] >= r) {
                        s_thr[t] = (unsigned)(B0 + (NBINS - 1 - (tid * 10 + j))) << 11;
                        break;
                    }
                    cum += loc10[j];
                }
            }
        }
    }
    __syncthreads();

    const float4* sc4 = reinterpret_cast<const float4*>(g_maxs + (size_t)b * NA);
    const int N4 = NA / 4;   // 12276
    int nfinal = 0;

    for (int round = 0; round < 2; round++) {
        const unsigned thr = s_thr[round];
        // ---- compaction: keys >= thr ----
        if (tid == 0) s_cnt = 0;
        __syncthreads();
        for (int i = tid; i < N4; i += NT) {
            float4 v = sc4[i];
            unsigned kk[4] = { __float_as_uint(v.x), __float_as_uint(v.y),
                               __float_as_uint(v.z), __float_as_uint(v.w) };
#pragma unroll
            for (int c = 0; c < 4; c++) {
                if (kk[c] > THR_BITS && kk[c] >= thr) {
                    int pos = atomicAdd(&s_cnt, 1);
                    int idx = i * 4 + c;
                    if (pos < CAND_CAP)
                        buf[pos] = ((ull)kk[c] << 32) |
                                   ((ull)(0xFFFFu - (unsigned)idx) << 16) |
                                   (ull)g_cls[(size_t)b * NA + idx];
                }
            }
        }
        __syncthreads();
        const int n = min(s_cnt, CAND_CAP);
        if (round == 0 && n > 1024) continue;   // fast path can't hold it

        int SZ = 32;
        while (SZ < n) SZ <<= 1;
        const int L = min(K, n);                // NMS scan limit
        for (int i = n + tid; i < SZ; i += NT) buf[i] = 0ULL;
        __syncthreads();

        // ---- bitonic sort (descending, SZ keys) ----
        for (int k2 = 2; k2 <= SZ; k2 <<= 1) {
            for (int j = k2 >> 1; j >= 32; j >>= 1) {
                for (int t = tid; t < (SZ >> 1); t += NT) {
                    int i = ((t & ~(j - 1)) << 1) | (t & (j - 1));
                    int ixj = i + j;
                    bool desc = ((i & k2) == 0);
                    ull a = buf[i], c2 = buf[ixj];
                    if (desc ? (a < c2) : (a > c2)) { buf[i] = c2; buf[ixj] = a; }
                }
                __syncthreads();
            }
            const int jstart = min(k2 >> 1, 16);
            for (int e = tid; e < SZ; e += NT) {
                ull v = buf[e];
                bool desc = ((e & k2) == 0);
                for (int j = jstart; j; j >>= 1) {
                    ull o = __shfl_xor_sync(0xffffffffu, v, j);
                    bool lower = (lane & j) == 0;
                    if (desc == lower) v = (v > o) ? v : o;
                    else               v = (v < o) ? v : o;
                }
                buf[e] = v;
            }
            __syncthreads();
        }

        // ---- decode the first L candidates ----
        for (int i = tid; i < L; i += NT) {
            ull key = buf[i];
            unsigned idx = 0xFFFFu - (unsigned)((key >> 16) & 0xFFFFu);
            float score = __uint_as_float((unsigned)(key >> 32));
            float4 an = reinterpret_cast<const float4*>(anchors)[idx];             // y1,x1,y2,x2
            float4 lp = reinterpret_cast<const float4*>(loc)[(size_t)b * NA + idx]; // dy,dx,dh,dw
            float ya = (an.x + an.z) * 0.5f, xa = (an.y + an.w) * 0.5f;
            float ha = an.z - an.x, wa = an.w - an.y;
            float hh = expf(lp.z) * ha;
            float ww = expf(lp.w) * wa;
            float yc = lp.x * ha + ya;
            float xc = lp.y * wa + xa;
            float x1 = fminf(fmaxf(xc - 0.5f * ww, 0.f), IMGF);
            float y1 = fminf(fmaxf(yc - 0.5f * hh, 0.f), IMGF);
            float x2 = fminf(fmaxf(xc + 0.5f * ww, 0.f), IMGF);
            float y2 = fminf(fmaxf(yc + 0.5f * hh, 0.f), IMGF);
            sbox[i] = make_float4(x1, y1, x2, y2);
            sval[i] = score;
            scls[i] = (int)(key & 0xFFFFu);
        }
        __syncthreads();   // buf (keys) now dead; adj may reuse its space

        // ---- parallel adjacency for top MC candidates ----
        const int MC = min(L, M_FAST);
#pragma unroll
        for (int r = 0; r < 8; r++) {
            int i = w * 8 + r;
            if (i < MC) {
                float4 bi = sbox[i];
                int ci = scls[i];
                float ai = (bi.z - bi.x) * (bi.w - bi.y);
                unsigned stash = 0;
#pragma unroll
                for (int jw = 0; jw < 8; jw++) {
                    int j = (jw << 5) + lane;
                    bool p = false;
                    if (j > i && j < MC && scls[j] == ci) {
                        float4 bj = sbox[j];
                        float xx1 = fmaxf(bi.x, bj.x), yy1 = fmaxf(bi.y, bj.y);
                        float xx2 = fminf(bi.z, bj.z), yy2 = fminf(bi.w, bj.w);
                        float in = fmaxf(xx2 - xx1, 0.f) * fmaxf(yy2 - yy1, 0.f);
                        float aj = (bj.z - bj.x) * (bj.w - bj.y);
                        p = in > IOU_THR * (ai + aj - in + 1e-8f);
                    }
                    unsigned word = __ballot_sync(0xffffffffu, p);
                    if (lane == jw) stash = word;
                }
                if (lane < 8) adj[i * 8 + lane] = stash;
            } else {
                __ballot_sync(0xffffffffu, false);  // keep warp converged cheaply
            }
        }
        if (tid == 0) s_nk = 0;
        __syncthreads();

        // ---- greedy scan over bitmask (warp 0) ----
        if (tid < 32) {
            unsigned sup = 0;      // lane l owns suppression bits [32l, 32l+32)
            int nk = 0;
            int i = 0;
            for (; i < MC && nk < K_OUT; i++) {
                unsigned sb = (lane == (i >> 5)) ? ((sup >> (i & 31)) & 1u) : 0u;
                if (__ballot_sync(0xffffffffu, sb != 0u) == 0u) {
                    if (lane < 8) sup |= adj[i * 8 + lane];
                    if (lane == 0) kept[nk] = (short)i;
                    nk++;
                }
            }
            // materialize kept boxes (needed for fallback & harmless otherwise)
            for (int s2 = lane; s2 < nk; s2 += 32) {
                int ki = kept[s2];
                float4 bb = sbox[ki];
                kbox[s2] = bb;
                karea[s2] = (bb.z - bb.x) * (bb.w - bb.y);
                kcls[s2] = scls[ki];
            }
            __syncwarp();
            // serial fallback for candidates beyond the adjacency window (rare)
            for (int i2 = MC; i2 < L && nk < K_OUT; i2++) {
                float4 bi = sbox[i2];
                int ci = scls[i2];
                float ai = (bi.z - bi.x) * (bi.w - bi.y);
                bool sup2 = false;
#pragma unroll
                for (int r = 0; r < 4; r++) {
                    int slot = lane + (r << 5);
                    if (slot < nk && kcls[slot] == ci) {
                        float4 bj = kbox[slot];
                        float xx1 = fmaxf(bi.x, bj.x), yy1 = fmaxf(bi.y, bj.y);
                        float xx2 = fminf(bi.z, bj.z), yy2 = fminf(bi.w, bj.w);
                        float in = fmaxf(xx2 - xx1, 0.f) * fmaxf(yy2 - yy1, 0.f);
                        if (in > IOU_THR * (ai + karea[slot] - in + 1e-8f)) sup2 = true;
                    }
                }
                if (__ballot_sync(0xffffffffu, sup2) == 0u) {
                    if (lane == 0) {
                        kbox[nk] = bi; karea[nk] = ai; kcls[nk] = ci; kept[nk] = (short)i2;
                    }
                    __syncwarp();
                    nk++;
                }
            }
            if (lane == 0) s_nk = nk;
        }
        __syncthreads();
        nfinal = s_nk;
        // done if: full round, or found K_OUT, or fast set already covered top-K
        if (round == 1 || nfinal >= K_OUT || n >= K) break;
    }

    const int nk = nfinal;
    // ---- output: boxes [B,100,4] | scores [B,100] | labels [B,100] ----
    float* oboxes  = out + (size_t)b * K_OUT * 4;
    float* oscores = out + (size_t)NB * K_OUT * 4 + (size_t)b * K_OUT;
    float* olabels = out + (size_t)NB * K_OUT * 5 + (size_t)b * K_OUT;
    for (int s2 = tid; s2 < K_OUT; s2 += NT) {
        if (s2 < nk) {
            int i = kept[s2];
            float4 bb = sbox[i];
            oboxes[s2 * 4 + 0] = bb.x;
            oboxes[s2 * 4 + 1] = bb.y;
            oboxes[s2 * 4 + 2] = bb.z;
            oboxes[s2 * 4 + 3] = bb.w;
            oscores[s2] = sval[i];
            olabels[s2] = (float)scls[i];
        } else {
            oboxes[s2 * 4 + 0] = 0.f;
            oboxes[s2 * 4 + 1] = 0.f;
            oboxes[s2 * 4 + 2] = 1.f;
            oboxes[s2 * 4 + 3] = 1.f;
            oscores[s2] = 0.f;
            olabels[s2] = -1.f;
        }
    }
}

// ---------------- launch ----------------
extern "C" void kernel_launch(void* const* d_in, const int* in_sizes, int n_in,
                              void* d_out, int out_size) {
    const float* cls     = (const float*)d_in[0];
    const float* loc     = (const float*)d_in[1];
    const float* anchors = (const float*)d_in[2];
    float* out = (float*)d_out;

    k_maxarg<<<NROW / ROWS_PB, 512>>>(cls);   // 3069 blocks
    k_fused<<<NB, 1024>>>(loc, anchors, out);
}

// round 7
// speedup vs baseline: 1.3643x; 1.0576x over previous
#include <cuda_runtime.h>
#include <cstdint>

#define NB 8
#define NA 49104
#define NC 90
#define IMGF 512.0f
#define SCORE_THR 0.2f
#define THR_BITS 0x3E4CCCCDu   /* bits of 0.2f; valid <=> bits > THR_BITS */
#define FINE_CUT 0x3F7F0000u   /* ~0.99609: fine-bin region start */
#define NCOARSE 9799           /* (FINE_CUT - THR_BITS) >> 11, +1 */
#define NFINE 1024
#define NBINS (NCOARSE + NFINE)   /* 10823 */
#define BINS_PT 11             /* ceil(NBINS/1024) */
#define IOU_THR 0.2f
#define K_PRE 1000
#define K_OUT 100
#define NROW (NB * NA)
#define CAND_CAP 2048
#define M_FAST 192             /* fast-path rank target */
#define RPW 8

typedef unsigned long long ull;

// ---------------- scratch (zero-init at load; k_fused re-zeroes g_hist) ----
__device__ float g_maxs[NROW];
__device__ unsigned char g_cls[NROW];
__device__ int g_hist[NB * NBINS];

__device__ __forceinline__ unsigned bin_floor(int bin) {
    return (bin >= NCOARSE) ? FINE_CUT + ((unsigned)(bin - NCOARSE) << 6)
                            : THR_BITS + ((unsigned)bin << 11);
}

// ---------------- K1: direct warp-per-row max/argmax + two-tier histogram ----
__global__ void __launch_bounds__(512) k_maxarg(const float* __restrict__ cls) {
    const int warp = (blockIdx.x * blockDim.x + threadIdx.x) >> 5;
    const int lane = threadIdx.x & 31;
    const int row0 = warp * RPW;
    const bool has2 = lane < 13;

    float2 a[RPW], c2[RPW];
#pragma unroll
    for (int r = 0; r < RPW; r++) {
        const float2* p = reinterpret_cast<const float2*>(cls + (size_t)(row0 + r) * NC);
        a[r] = p[lane];
        c2[r] = has2 ? p[lane + 32] : make_float2(0.f, 0.f);
    }
#pragma unroll
    for (int r = 0; r < RPW; r++) {
        unsigned u0 = __float_as_uint(a[r].x), u1 = __float_as_uint(a[r].y);
        unsigned u2 = __float_as_uint(c2[r].x), u3 = __float_as_uint(c2[r].y);
        unsigned mx = max(max(u0, u1), max(u2, u3));
        mx = __reduce_max_sync(0xffffffffu, mx);
        unsigned c = 0xFFu;
        if (u3 == mx) c = 2 * lane + 65;   // larger col first; smaller overwrite
        if (u2 == mx) c = 2 * lane + 64;
        if (u1 == mx) c = 2 * lane + 1;
        if (u0 == mx) c = 2 * lane;
        c = __reduce_min_sync(0xffffffffu, c);
        if (lane == 0) {
            int grow = row0 + r;
            g_maxs[grow] = __uint_as_float(mx);
            g_cls[grow] = (unsigned char)c;
            if (mx > THR_BITS) {
                int b = grow / NA;
                unsigned bin = (mx >= FINE_CUT)
                                 ? (unsigned)NCOARSE + min((mx - FINE_CUT) >> 6, (unsigned)(NFINE - 1))
                                 : (mx - THR_BITS) >> 11;
                atomicAdd(&g_hist[b * NBINS + bin], 1);
            }
        }
    }
}

// ---------------- K2: fused thresholds + compact + sort + bitmask NMS ------
__global__ void __launch_bounds__(1024, 1)
k_fused(const float* __restrict__ loc,
        const float* __restrict__ anchors,
        float* __restrict__ out) {
    const int b = blockIdx.x;
    const int tid = threadIdx.x;
    const int lane = tid & 31, w = tid >> 5;
    const int NT = 1024;

    __shared__ ull buf[CAND_CAP];           // sort keys; reused as adj after decode
    __shared__ float4 sbox[1024];
    __shared__ float sval[1024];
    __shared__ int scls[1024];
    __shared__ float4 kbox[K_OUT];
    __shared__ float karea[K_OUT];
    __shared__ int kcls[K_OUT];
    __shared__ short kept[K_OUT];
    __shared__ int wtot[32];
    __shared__ int s_nk, s_cnt;
    __shared__ unsigned s_thr[2];           // [0]: rank-m (fast), [1]: rank-K (full)

    unsigned* adj = reinterpret_cast<unsigned*>(buf);   // adj[i*8 + w32], 256x8

    // ---- thresholds from histogram (each thread owns BINS_PT descending bins) ----
    int* h = g_hist + b * NBINS;
    int loc10[BINS_PT];
    int ssum = 0;
#pragma unroll
    for (int j = 0; j < BINS_PT; j++) {
        int bi = NBINS - 1 - (tid * BINS_PT + j);
        int v = 0;
        if (bi >= 0) { v = h[bi]; h[bi] = 0; }   // read + re-zero (disjoint per thread)
        loc10[j] = v;
        ssum += v;
    }
    int ps = ssum;
#pragma unroll
    for (int off = 1; off < 32; off <<= 1) {
        int t = __shfl_up_sync(0xffffffffu, ps, off);
        if (lane >= off) ps += t;
    }
    if (lane == 31) wtot[w] = ps;
    if (tid == 0) { s_thr[0] = 0xFFFFFFFFu; s_thr[1] = 0xFFFFFFFFu; s_nk = 0; }
    __syncthreads();
    if (w == 0) {
        int v = wtot[lane];
#pragma unroll
        for (int off = 1; off < 32; off <<= 1) {
            int t = __shfl_up_sync(0xffffffffu, v, off);
            if (lane >= off) v += t;
        }
        wtot[lane] = v;
    }
    __syncthreads();

    const int total = wtot[31];
    const int K = min(K_PRE, total);
    const int m = min(M_FAST, K);
    if (K > 0) {
        int above = (ps - ssum) + (w > 0 ? wtot[w - 1] : 0);
#pragma unroll
        for (int t = 0; t < 2; t++) {
            int r = (t == 0) ? m : K;
            if (above < r && r <= above + ssum) {
                int cum = above;
#pragma unroll
                for (int j = 0; j < BINS_PT; j++) {
                    if (cum + loc10[j] >= r) {
                        s_thr[t] = bin_floor(NBINS - 1 - (tid * BINS_PT + j));
                        break;
                    }
                    cum += loc10[j];
                }
            }
        }
    }
    __syncthreads();

    const float4* sc4 = reinterpret_cast<const float4*>(g_maxs + (size_t)b * NA);
    const int N4 = NA / 4;   // 12276
    int nfinal = 0;

    for (int round = 0; round < 2; round++) {
        const unsigned thr = s_thr[round];
        // ---- compaction: keys >= thr ----
        if (tid == 0) s_cnt = 0;
        __syncthreads();
        for (int i = tid; i < N4; i += NT) {
            float4 v = sc4[i];
            unsigned kk[4] = { __float_as_uint(v.x), __float_as_uint(v.y),
                               __float_as_uint(v.z), __float_as_uint(v.w) };
#pragma unroll
            for (int c = 0; c < 4; c++) {
                if (kk[c] > THR_BITS && kk[c] >= thr) {
                    int pos = atomicAdd(&s_cnt, 1);
                    int idx = i * 4 + c;
                    if (pos < CAND_CAP)
                        buf[pos] = ((ull)kk[c] << 32) |
                                   ((ull)(0xFFFFu - (unsigned)idx) << 16) |
                                   (ull)g_cls[(size_t)b * NA + idx];
                }
            }
        }
        __syncthreads();
        const int n = min(s_cnt, CAND_CAP);
        if (round == 0 && n > 1024) continue;   // fast path can't hold it

        int SZ = 32;
        while (SZ < n) SZ <<= 1;
        const int L = min(K, n);                // NMS scan limit
        for (int i = n + tid; i < SZ; i += NT) buf[i] = 0ULL;
        __syncthreads();

        // ---- bitonic sort (descending, SZ keys) ----
        for (int k2 = 2; k2 <= SZ; k2 <<= 1) {
            for (int j = k2 >> 1; j >= 32; j >>= 1) {
                for (int t = tid; t < (SZ >> 1); t += NT) {
                    int i = ((t & ~(j - 1)) << 1) | (t & (j - 1));
                    int ixj = i + j;
                    bool desc = ((i & k2) == 0);
                    ull a = buf[i], c2 = buf[ixj];
                    if (desc ? (a < c2) : (a > c2)) { buf[i] = c2; buf[ixj] = a; }
                }
                __syncthreads();
            }
            const int jstart = min(k2 >> 1, 16);
            for (int e = tid; e < SZ; e += NT) {
                ull v = buf[e];
                bool desc = ((e & k2) == 0);
                for (int j = jstart; j; j >>= 1) {
                    ull o = __shfl_xor_sync(0xffffffffu, v, j);
                    bool lower = (lane & j) == 0;
                    if (desc == lower) v = (v > o) ? v : o;
                    else               v = (v < o) ? v : o;
                }
                buf[e] = v;
            }
            __syncthreads();
        }

        // ---- decode the first L candidates ----
        for (int i = tid; i < L; i += NT) {
            ull key = buf[i];
            unsigned idx = 0xFFFFu - (unsigned)((key >> 16) & 0xFFFFu);
            float score = __uint_as_float((unsigned)(key >> 32));
            float4 an = reinterpret_cast<const float4*>(anchors)[idx];             // y1,x1,y2,x2
            float4 lp = reinterpret_cast<const float4*>(loc)[(size_t)b * NA + idx]; // dy,dx,dh,dw
            float ya = (an.x + an.z) * 0.5f, xa = (an.y + an.w) * 0.5f;
            float ha = an.z - an.x, wa = an.w - an.y;
            float hh = expf(lp.z) * ha;
            float ww = expf(lp.w) * wa;
            float yc = lp.x * ha + ya;
            float xc = lp.y * wa + xa;
            float x1 = fminf(fmaxf(xc - 0.5f * ww, 0.f), IMGF);
            float y1 = fminf(fmaxf(yc - 0.5f * hh, 0.f), IMGF);
            float x2 = fminf(fmaxf(xc + 0.5f * ww, 0.f), IMGF);
            float y2 = fminf(fmaxf(yc + 0.5f * hh, 0.f), IMGF);
            sbox[i] = make_float4(x1, y1, x2, y2);
            sval[i] = score;
            scls[i] = (int)(key & 0xFFFFu);
        }
        __syncthreads();   // buf (keys) now dead; adj may reuse its space

        // ---- parallel adjacency for top MC candidates ----
        const int MC = min(L, 256);
#pragma unroll
        for (int r = 0; r < 8; r++) {
            int i = w * 8 + r;
            if (i < MC) {
                float4 bi = sbox[i];
                int ci = scls[i];
                float ai = (bi.z - bi.x) * (bi.w - bi.y);
                unsigned stash = 0;
#pragma unroll
                for (int jw = 0; jw < 8; jw++) {
                    int j = (jw << 5) + lane;
                    bool p = false;
                    if (j > i && j < MC && scls[j] == ci) {
                        float4 bj = sbox[j];
                        float xx1 = fmaxf(bi.x, bj.x), yy1 = fmaxf(bi.y, bj.y);
                        float xx2 = fminf(bi.z, bj.z), yy2 = fminf(bi.w, bj.w);
                        float in = fmaxf(xx2 - xx1, 0.f) * fmaxf(yy2 - yy1, 0.f);
                        float aj = (bj.z - bj.x) * (bj.w - bj.y);
                        p = in > IOU_THR * (ai + aj - in + 1e-8f);
                    }
                    unsigned word = __ballot_sync(0xffffffffu, p);
                    if (lane == jw) stash = word;
                }
                if (lane < 8) adj[i * 8 + lane] = stash;
            } else {
                __ballot_sync(0xffffffffu, false);  // keep warp converged cheaply
            }
        }
        if (tid == 0) s_nk = 0;
        __syncthreads();

        // ---- greedy scan over bitmask (warp 0) ----
        if (tid < 32) {
            unsigned sup = 0;      // lane l owns suppression bits [32l, 32l+32)
            int nk = 0;
            for (int i = 0; i < MC && nk < K_OUT; i++) {
                unsigned sb = (lane == (i >> 5)) ? ((sup >> (i & 31)) & 1u) : 0u;
                if (__ballot_sync(0xffffffffu, sb != 0u) == 0u) {
                    if (lane < 8) sup |= adj[i * 8 + lane];
                    if (lane == 0) kept[nk] = (short)i;
                    nk++;
                }
            }
            // materialize kept boxes (needed for fallback & harmless otherwise)
            for (int s2 = lane; s2 < nk; s2 += 32) {
                int ki = kept[s2];
                float4 bb = sbox[ki];
                kbox[s2] = bb;
                karea[s2] = (bb.z - bb.x) * (bb.w - bb.y);
                kcls[s2] = scls[ki];
            }
            __syncwarp();
            // serial fallback for candidates beyond the adjacency window (rare)
            for (int i2 = MC; i2 < L && nk < K_OUT; i2++) {
                float4 bi = sbox[i2];
                int ci = scls[i2];
                float ai = (bi.z - bi.x) * (bi.w - bi.y);
                bool sup2 = false;
#pragma unroll
                for (int r = 0; r < 4; r++) {
                    int slot = lane + (r << 5);
                    if (slot < nk && kcls[slot] == ci) {
                        float4 bj = kbox[slot];
                        float xx1 = fmaxf(bi.x, bj.x), yy1 = fmaxf(bi.y, bj.y);
                        float xx2 = fminf(bi.z, bj.z), yy2 = fminf(bi.w, bj.w);
                        float in = fmaxf(xx2 - xx1, 0.f) * fmaxf(yy2 - yy1, 0.f);
                        if (in > IOU_THR * (ai + karea[slot] - in + 1e-8f)) sup2 = true;
                    }
                }
                if (__ballot_sync(0xffffffffu, sup2) == 0u) {
                    if (lane == 0) {
                        kbox[nk] = bi; karea[nk] = ai; kcls[nk] = ci; kept[nk] = (short)i2;
                    }
                    __syncwarp();
                    nk++;
                }
            }
            if (lane == 0) s_nk = nk;
        }
        __syncthreads();
        nfinal = s_nk;
        // done if: full round, or found K_OUT, or fast set already covered top-K
        if (round == 1 || nfinal >= K_OUT || n >= K) break;
    }

    const int nk = nfinal;
    // ---- output: boxes [B,100,4] | scores [B,100] | labels [B,100] ----
    float* oboxes  = out + (size_t)b * K_OUT * 4;
    float* oscores = out + (size_t)NB * K_OUT * 4 + (size_t)b * K_OUT;
    float* olabels = out + (size_t)NB * K_OUT * 5 + (size_t)b * K_OUT;
    for (int s2 = tid; s2 < K_OUT; s2 += NT) {
        if (s2 < nk) {
            int i = kept[s2];
            float4 bb = sbox[i];
            oboxes[s2 * 4 + 0] = bb.x;
            oboxes[s2 * 4 + 1] = bb.y;
            oboxes[s2 * 4 + 2] = bb.z;
            oboxes[s2 * 4 + 3] = bb.w;
            oscores[s2] = sval[i];
            olabels[s2] = (float)scls[i];
        } else {
            oboxes[s2 * 4 + 0] = 0.f;
            oboxes[s2 * 4 + 1] = 0.f;
            oboxes[s2 * 4 + 2] = 1.f;
            oboxes[s2 * 4 + 3] = 1.f;
            oscores[s2] = 0.f;
            olabels[s2] = -1.f;
        }
    }
}

// ---------------- launch ----------------
extern "C" void kernel_launch(void* const* d_in, const int* in_sizes, int n_in,
                              void* d_out, int out_size) {
    const float* cls     = (const float*)d_in[0];
    const float* loc     = (const float*)d_in[1];
    const float* anchors = (const float*)d_in[2];
    float* out = (float*)d_out;

    // 512 threads = 16 warps * 8 rows = 128 rows/block; 392832/128 = 3069 blocks
    k_maxarg<<<NROW / (16 * RPW), 512>>>(cls);
    k_fused<<<NB, 1024>>>(loc, anchors, out);
}

// round 8
// speedup vs baseline: 1.7167x; 1.2583x over previous
#include <cuda_runtime.h>
#include <cstdint>

#define NB 8
#define NA 49104
#define NC 90
#define IMGF 512.0f
#define SCORE_THR 0.2f
#define THR_BITS 0x3E4CCCCDu   /* bits of 0.2f; valid <=> bits > THR_BITS */
#define FINE_CUT 0x3F7F0000u   /* ~0.99609: fine-bin region start */
#define STATIC_CUT 0x3F7FE000u /* fine bin 896; list pre-filter cut (~0.99951) */
#define NCOARSE 9799
#define NFINE 1024
#define NBINS (NCOARSE + NFINE)   /* 10823 */
#define BINS_PT 11
#define IOU_THR 0.2f
#define K_PRE 1000
#define K_OUT 100
#define NROW (NB * NA)
#define CAND_CAP 2048
#define M_FAST 192
#define GCAP 4096

typedef unsigned long long ull;

// -------- scratch (zero-init at load; k_fused re-zeroes g_hist/g_gcnt) -----
__device__ float g_maxs[NROW];
__device__ unsigned char g_cls[NROW];
__device__ int g_hist[NB * NBINS];
__device__ int g_gcnt[NB];
__device__ ull g_list[NB * GCAP];

__device__ __forceinline__ unsigned bin_floor(int bin) {
    return (bin >= NCOARSE) ? FINE_CUT + ((unsigned)(bin - NCOARSE) << 6)
                            : THR_BITS + ((unsigned)bin << 11);
}

// ---------------- K1: thread-per-row max/argmax + histogram + list ---------
__global__ void __launch_bounds__(256) k_maxarg(const float* __restrict__ cls) {
    int t = blockIdx.x * blockDim.x + threadIdx.x;
    if (t >= NROW) return;
    const float2* row = reinterpret_cast<const float2*>(cls + (size_t)t * NC);
    unsigned bestu = 0u;
    int bi = 0;
#pragma unroll
    for (int i = 0; i < NC / 2; i++) {
        float2 v = row[i];
        unsigned u0 = __float_as_uint(v.x), u1 = __float_as_uint(v.y);
        if (u0 > bestu) { bestu = u0; bi = 2 * i; }
        if (u1 > bestu) { bestu = u1; bi = 2 * i + 1; }
    }
    g_maxs[t] = __uint_as_float(bestu);
    g_cls[t] = (unsigned char)bi;
    if (bestu > THR_BITS) {
        int b = t / NA;
        unsigned bin = (bestu >= FINE_CUT)
                         ? (unsigned)NCOARSE + min((bestu - FINE_CUT) >> 6, (unsigned)(NFINE - 1))
                         : (bestu - THR_BITS) >> 11;
        atomicAdd(&g_hist[b * NBINS + bin], 1);
        if (bestu >= STATIC_CUT) {
            int idx = t - b * NA;
            int pos = atomicAdd(&g_gcnt[b], 1);
            if (pos < GCAP)
                g_list[b * GCAP + pos] = ((ull)bestu << 32) |
                                         ((ull)(0xFFFFu - (unsigned)idx) << 16) | (ull)bi;
        }
    }
}

// ---------------- K2: fused thresholds + compact + sort + bitmask NMS ------
__global__ void __launch_bounds__(1024, 1)
k_fused(const float* __restrict__ loc,
        const float* __restrict__ anchors,
        float* __restrict__ out) {
    const int b = blockIdx.x;
    const int tid = threadIdx.x;
    const int lane = tid & 31, w = tid >> 5;
    const int NT = 1024;

    __shared__ ull buf[CAND_CAP];           // sort keys; reused as adj after decode
    __shared__ float4 sbox[1024];
    __shared__ float sval[1024];
    __shared__ int scls[1024];
    __shared__ float4 kbox[K_OUT];
    __shared__ float karea[K_OUT];
    __shared__ int kcls[K_OUT];
    __shared__ short kept[K_OUT];
    __shared__ int wtot[32];
    __shared__ int s_nk, s_cnt, s_gc, s_K;
    __shared__ unsigned s_thr[2];

    unsigned* adj = reinterpret_cast<unsigned*>(buf);

    int* h = g_hist + b * NBINS;
    if (tid == 0) {
        s_gc = g_gcnt[b];
        s_thr[0] = 0xFFFFFFFFu; s_thr[1] = 0xFFFFFFFFu;
        s_nk = 0; s_K = 0;
    }

    // ---- fast threshold pass: fine region only, coalesced ----
    int fineval = h[NBINS - 1 - tid];       // tid t owns fine bin NBINS-1-t (desc)
    int ps = fineval;
#pragma unroll
    for (int off = 1; off < 32; off <<= 1) {
        int t2 = __shfl_up_sync(0xffffffffu, ps, off);
        if (lane >= off) ps += t2;
    }
    if (lane == 31) wtot[w] = ps;
    __syncthreads();
    if (w == 0) {
        int v = wtot[lane];
#pragma unroll
        for (int off = 1; off < 32; off <<= 1) {
            int t2 = __shfl_up_sync(0xffffffffu, v, off);
            if (lane >= off) v += t2;
        }
        wtot[lane] = v;
    }
    __syncthreads();
    const int fine_total = wtot[31];
    bool fine_ok = (fine_total >= K_PRE);
    int K;
    if (fine_ok) {
        K = K_PRE;
        int above = (ps - fineval) + (w > 0 ? wtot[w - 1] : 0);
        const int m = M_FAST;   // < K_PRE
#pragma unroll
        for (int t2 = 0; t2 < 2; t2++) {
            int r = (t2 == 0) ? m : K_PRE;
            if (above < r && r <= above + fineval)
                s_thr[t2] = FINE_CUT + ((unsigned)(1023 - tid) << 6);
        }
        if (tid == 0) s_K = K_PRE;
        __syncthreads();
    } else {
        // ---- slow path: full blocked histogram read ----
        __syncthreads();
        int loc10[BINS_PT];
        int ssum = 0;
#pragma unroll
        for (int j = 0; j < BINS_PT; j++) {
            int bi = NBINS - 1 - (tid * BINS_PT + j);
            loc10[j] = (bi >= 0) ? h[bi] : 0;
            ssum += loc10[j];
        }
        int ps2 = ssum;
#pragma unroll
        for (int off = 1; off < 32; off <<= 1) {
            int t2 = __shfl_up_sync(0xffffffffu, ps2, off);
            if (lane >= off) ps2 += t2;
        }
        if (lane == 31) wtot[w] = ps2;
        __syncthreads();
        if (w == 0) {
            int v = wtot[lane];
#pragma unroll
            for (int off = 1; off < 32; off <<= 1) {
                int t2 = __shfl_up_sync(0xffffffffu, v, off);
                if (lane >= off) v += t2;
            }
            wtot[lane] = v;
        }
        __syncthreads();
        const int total = wtot[31];
        K = min(K_PRE, total);
        if (tid == 0) s_K = K;
        if (K > 0) {
            int above = (ps2 - ssum) + (w > 0 ? wtot[w - 1] : 0);
            const int m = min(M_FAST, K);
#pragma unroll
            for (int t2 = 0; t2 < 2; t2++) {
                int r = (t2 == 0) ? m : K;
                if (above < r && r <= above + ssum) {
                    int cum = above;
#pragma unroll
                    for (int j = 0; j < BINS_PT; j++) {
                        if (cum + loc10[j] >= r) {
                            s_thr[t2] = bin_floor(NBINS - 1 - (tid * BINS_PT + j));
                            break;
                        }
                        cum += loc10[j];
                    }
                }
            }
        }
        __syncthreads();
    }
    K = s_K;
    const int gc = s_gc;
    const bool use_list = fine_ok && (s_thr[1] >= STATIC_CUT) && (gc > 0) && (gc <= GCAP);

    // ---- re-zero histogram (coalesced) + list counter for next run ----
    for (int i = tid; i < NBINS; i += NT) h[i] = 0;
    if (tid == 0) g_gcnt[b] = 0;

    const float4* sc4 = reinterpret_cast<const float4*>(g_maxs + (size_t)b * NA);
    const int N4 = NA / 4;
    int nfinal = 0;

    for (int round = 0; round < 2; round++) {
        const unsigned thr = s_thr[round];
        if (tid == 0) s_cnt = 0;
        __syncthreads();
        if (use_list) {
            const ull* lst = g_list + (size_t)b * GCAP;
            for (int i = tid; i < gc; i += NT) {
                ull key = lst[i];
                if ((unsigned)(key >> 32) >= thr) {
                    int pos = atomicAdd(&s_cnt, 1);
                    if (pos < CAND_CAP) buf[pos] = key;
                }
            }
        } else {
            for (int i = tid; i < N4; i += NT) {
                float4 v = sc4[i];
                unsigned kk[4] = { __float_as_uint(v.x), __float_as_uint(v.y),
                                   __float_as_uint(v.z), __float_as_uint(v.w) };
#pragma unroll
                for (int c = 0; c < 4; c++) {
                    if (kk[c] > THR_BITS && kk[c] >= thr) {
                        int pos = atomicAdd(&s_cnt, 1);
                        int idx = i * 4 + c;
                        if (pos < CAND_CAP)
                            buf[pos] = ((ull)kk[c] << 32) |
                                       ((ull)(0xFFFFu - (unsigned)idx) << 16) |
                                       (ull)g_cls[(size_t)b * NA + idx];
                    }
                }
            }
        }
        __syncthreads();
        const int n = min(s_cnt, CAND_CAP);
        if (round == 0 && n > 1024) continue;

        int SZ = 32;
        while (SZ < n) SZ <<= 1;
        const int L = min(K, n);
        for (int i = n + tid; i < SZ; i += NT) buf[i] = 0ULL;
        __syncthreads();

        // ---- bitonic sort (descending, SZ keys) ----
        for (int k2 = 2; k2 <= SZ; k2 <<= 1) {
            for (int j = k2 >> 1; j >= 32; j >>= 1) {
                for (int t2 = tid; t2 < (SZ >> 1); t2 += NT) {
                    int i = ((t2 & ~(j - 1)) << 1) | (t2 & (j - 1));
                    int ixj = i + j;
                    bool desc = ((i & k2) == 0);
                    ull a = buf[i], c2 = buf[ixj];
                    if (desc ? (a < c2) : (a > c2)) { buf[i] = c2; buf[ixj] = a; }
                }
                __syncthreads();
            }
            const int jstart = min(k2 >> 1, 16);
            for (int e = tid; e < SZ; e += NT) {
                ull v = buf[e];
                bool desc = ((e & k2) == 0);
                for (int j = jstart; j; j >>= 1) {
                    ull o = __shfl_xor_sync(0xffffffffu, v, j);
                    bool lower = (lane & j) == 0;
                    if (desc == lower) v = (v > o) ? v : o;
                    else               v = (v < o) ? v : o;
                }
                buf[e] = v;
            }
            __syncthreads();
        }

        // ---- decode the first L candidates ----
        for (int i = tid; i < L; i += NT) {
            ull key = buf[i];
            unsigned idx = 0xFFFFu - (unsigned)((key >> 16) & 0xFFFFu);
            float score = __uint_as_float((unsigned)(key >> 32));
            float4 an = reinterpret_cast<const float4*>(anchors)[idx];
            float4 lp = reinterpret_cast<const float4*>(loc)[(size_t)b * NA + idx];
            float ya = (an.x + an.z) * 0.5f, xa = (an.y + an.w) * 0.5f;
            float ha = an.z - an.x, wa = an.w - an.y;
            float hh = expf(lp.z) * ha;
            float ww = expf(lp.w) * wa;
            float yc = lp.x * ha + ya;
            float xc = lp.y * wa + xa;
            float x1 = fminf(fmaxf(xc - 0.5f * ww, 0.f), IMGF);
            float y1 = fminf(fmaxf(yc - 0.5f * hh, 0.f), IMGF);
            float x2 = fminf(fmaxf(xc + 0.5f * ww, 0.f), IMGF);
            float y2 = fminf(fmaxf(yc + 0.5f * hh, 0.f), IMGF);
            sbox[i] = make_float4(x1, y1, x2, y2);
            sval[i] = score;
            scls[i] = (int)(key & 0xFFFFu);
        }
        __syncthreads();   // keys in buf now dead; adj reuses the space

        // ---- parallel adjacency for top MC candidates (class-gated) ----
        const int MC = min(L, 256);
#pragma unroll
        for (int r = 0; r < 8; r++) {
            int i = w * 8 + r;
            if (i < MC) {
                float4 bi = sbox[i];
                int ci = scls[i];
                float ai = (bi.z - bi.x) * (bi.w - bi.y);
                unsigned stash = 0;
#pragma unroll
                for (int jw = 0; jw < 8; jw++) {
                    int j = (jw << 5) + lane;
                    bool ce = (j > i && j < MC && scls[j] == ci);
                    unsigned word = 0;
                    if (__any_sync(0xffffffffu, ce)) {
                        bool p = false;
                        if (ce) {
                            float4 bj = sbox[j];
                            float xx1 = fmaxf(bi.x, bj.x), yy1 = fmaxf(bi.y, bj.y);
                            float xx2 = fminf(bi.z, bj.z), yy2 = fminf(bi.w, bj.w);
                            float in = fmaxf(xx2 - xx1, 0.f) * fmaxf(yy2 - yy1, 0.f);
                            float aj = (bj.z - bj.x) * (bj.w - bj.y);
                            p = in > IOU_THR * (ai + aj - in + 1e-8f);
                        }
                        word = __ballot_sync(0xffffffffu, p);
                    }
                    if (lane == jw) stash = word;
                }
                if (lane < 8) adj[i * 8 + lane] = stash;
            } else {
                __any_sync(0xffffffffu, false);
            }
        }
        if (tid == 0) s_nk = 0;
        __syncthreads();

        // ---- greedy scan over bitmask (warp 0) ----
        if (tid < 32) {
            unsigned sup = 0;
            int nk = 0;
            for (int i = 0; i < MC && nk < K_OUT; i++) {
                unsigned sb = (lane == (i >> 5)) ? ((sup >> (i & 31)) & 1u) : 0u;
                if (__ballot_sync(0xffffffffu, sb != 0u) == 0u) {
                    if (lane < 8) sup |= adj[i * 8 + lane];
                    if (lane == 0) kept[nk] = (short)i;
                    nk++;
                }
            }
            for (int s2 = lane; s2 < nk; s2 += 32) {
                int ki = kept[s2];
                float4 bb = sbox[ki];
                kbox[s2] = bb;
                karea[s2] = (bb.z - bb.x) * (bb.w - bb.y);
                kcls[s2] = scls[ki];
            }
            __syncwarp();
            for (int i2 = MC; i2 < L && nk < K_OUT; i2++) {
                float4 bi = sbox[i2];
                int ci = scls[i2];
                float ai = (bi.z - bi.x) * (bi.w - bi.y);
                bool sup2 = false;
#pragma unroll
                for (int r = 0; r < 4; r++) {
                    int slot = lane + (r << 5);
                    if (slot < nk && kcls[slot] == ci) {
                        float4 bj = kbox[slot];
                        float xx1 = fmaxf(bi.x, bj.x), yy1 = fmaxf(bi.y, bj.y);
                        float xx2 = fminf(bi.z, bj.z), yy2 = fminf(bi.w, bj.w);
                        float in = fmaxf(xx2 - xx1, 0.f) * fmaxf(yy2 - yy1, 0.f);
                        if (in > IOU_THR * (ai + karea[slot] - in + 1e-8f)) sup2 = true;
                    }
                }
                if (__ballot_sync(0xffffffffu, sup2) == 0u) {
                    if (lane == 0) {
                        kbox[nk] = bi; karea[nk] = ai; kcls[nk] = ci; kept[nk] = (short)i2;
                    }
                    __syncwarp();
                    nk++;
                }
            }
            if (lane == 0) s_nk = nk;
        }
        __syncthreads();
        nfinal = s_nk;
        if (round == 1 || nfinal >= K_OUT || n >= K) break;
    }

    const int nk = nfinal;
    float* oboxes  = out + (size_t)b * K_OUT * 4;
    float* oscores = out + (size_t)NB * K_OUT * 4 + (size_t)b * K_OUT;
    float* olabels = out + (size_t)NB * K_OUT * 5 + (size_t)b * K_OUT;
    for (int s2 = tid; s2 < K_OUT; s2 += NT) {
        if (s2 < nk) {
            int i = kept[s2];
            float4 bb = sbox[i];
            oboxes[s2 * 4 + 0] = bb.x;
            oboxes[s2 * 4 + 1] = bb.y;
            oboxes[s2 * 4 + 2] = bb.z;
            oboxes[s2 * 4 + 3] = bb.w;
            oscores[s2] = sval[i];
            olabels[s2] = (float)scls[i];
        } else {
            oboxes[s2 * 4 + 0] = 0.f;
            oboxes[s2 * 4 + 1] = 0.f;
            oboxes[s2 * 4 + 2] = 1.f;
            oboxes[s2 * 4 + 3] = 1.f;
            oscores[s2] = 0.f;
            olabels[s2] = -1.f;
        }
    }
}

// ---------------- launch ----------------
extern "C" void kernel_launch(void* const* d_in, const int* in_sizes, int n_in,
                              void* d_out, int out_size) {
    const float* cls     = (const float*)d_in[0];
    const float* loc     = (const float*)d_in[1];
    const float* anchors = (const float*)d_in[2];
    float* out = (float*)d_out;

    k_maxarg<<<(NROW + 255) / 256, 256>>>(cls);
    k_fused<<<NB, 1024>>>(loc, anchors, out);
}